// round 16
// baseline (speedup 1.0000x reference)
#include <cuda_runtime.h>
#include <cuda_fp16.h>
#include <mma.h>

using namespace nvcuda;

typedef unsigned long long u64;

#define NMAX 50048
#define EMAX 1600000

__device__ int    g_deg[NMAX];      // statically zero; restored to zero by k_scan each call
__device__ int    g_off[NMAX + 1];
__device__ int    g_agg[64];        // re-zeroed by k_hist each call
__device__ int    g_rank[EMAX];     // within-bucket rank per edge (from hist atomics)
__device__ int    g_ssrc[EMAX];
__device__ __half g_Ph[(size_t)NMAX * 128];
__device__ __half g_Qh[(size_t)NMAX * 128];
__device__ float  g_H[(size_t)NMAX * 128];

// ---------------- CSR build ----------------

// 8 edges/thread. Atomic returns = within-bucket rank, stored coalesced (int4).
__global__ void k_hist(const int* __restrict__ dst, int E) {
    if (blockIdx.x == 0 && threadIdx.x < 64) g_agg[threadIdx.x] = 0;
    int i0 = (blockIdx.x * blockDim.x + threadIdx.x) * 8;
    if (i0 + 7 < E) {
        int4 d0 = *(const int4*)(dst + i0);
        int4 d1 = *(const int4*)(dst + i0 + 4);
        int4 r0, r1;
        r0.x = atomicAdd(&g_deg[d0.x], 1);
        r0.y = atomicAdd(&g_deg[d0.y], 1);
        r0.z = atomicAdd(&g_deg[d0.z], 1);
        r0.w = atomicAdd(&g_deg[d0.w], 1);
        r1.x = atomicAdd(&g_deg[d1.x], 1);
        r1.y = atomicAdd(&g_deg[d1.y], 1);
        r1.z = atomicAdd(&g_deg[d1.z], 1);
        r1.w = atomicAdd(&g_deg[d1.w], 1);
        *(int4*)(g_rank + i0) = r0;
        *(int4*)(g_rank + i0 + 4) = r1;
    } else {
        for (int i = i0; i < E; ++i) g_rank[i] = atomicAdd(&g_deg[dst[i]], 1);
    }
}

// Single-pass exclusive scan over g_deg (nb <= 64 blocks, all wave-1 resident).
__global__ void k_scan(int N) {
    int idx = blockIdx.x * 1024 + threadIdx.x;
    int lane = threadIdx.x & 31, wid = threadIdx.x >> 5;
    int v = (idx < N) ? g_deg[idx] : 0;
    if (idx < N) g_deg[idx] = 0;   // restore initial state for next invocation
    int val = v;
    #pragma unroll
    for (int d = 1; d < 32; d <<= 1) {
        int t = __shfl_up_sync(0xffffffffu, val, d);
        if (lane >= d) val += t;
    }
    __shared__ int ws[32];
    __shared__ int partial[2];
    if (lane == 31) ws[wid] = val;
    __syncthreads();
    if (wid == 0) {
        int s = ws[lane];
        #pragma unroll
        for (int d = 1; d < 32; d <<= 1) {
            int t = __shfl_up_sync(0xffffffffu, s, d);
            if (lane >= d) s += t;
        }
        ws[lane] = s;
        if (lane == 31) atomicExch(&g_agg[blockIdx.x], s + 1);  // publish block total
    }
    if (threadIdx.x < 64) {
        int a = 0;
        if (threadIdx.x < blockIdx.x) {
            while ((a = atomicAdd(&g_agg[threadIdx.x], 0)) == 0) { }
            a -= 1;
        }
        #pragma unroll
        for (int d = 16; d > 0; d >>= 1) a += __shfl_down_sync(0xffffffffu, a, d);
        if (lane == 0) partial[wid] = a;
    }
    __syncthreads();
    int base = partial[0] + partial[1] + (wid ? ws[wid - 1] : 0);
    int excl = base + val - v;
    if (idx < N) g_off[idx] = excl;
    if (idx == N - 1) g_off[N] = excl + v;
}

// Atomic-free scatter: pos = off[dst] + rank. Pure loads + random store, MLP=4.
__global__ void k_scatter(const int* __restrict__ src, const int* __restrict__ dst, int E) {
    int i0 = (blockIdx.x * blockDim.x + threadIdx.x) * 4;
    if (i0 + 3 < E) {
        int4 d = *(const int4*)(dst + i0);
        int4 r = *(const int4*)(g_rank + i0);
        int4 s = *(const int4*)(src + i0);
        int p0 = g_off[d.x] + r.x;
        int p1 = g_off[d.y] + r.y;
        int p2 = g_off[d.z] + r.z;
        int p3 = g_off[d.w] + r.w;
        g_ssrc[p0] = s.x;
        g_ssrc[p1] = s.y;
        g_ssrc[p2] = s.z;
        g_ssrc[p3] = s.w;
    } else {
        for (int i = i0; i < E; ++i)
            g_ssrc[g_off[dst[i]] + g_rank[i]] = src[i];
    }
}

// ---------------- Node transform (tensor cores) ----------------
// [P|Q] = A[N,80] @ Wc[80,256], fp16 in / fp32 acc.
// Wc cols [0,128) = W1a - W1b (P, +b1 at epilogue); cols [128,256) = W1b (Q).
// Block: 8 warps, 64 nodes x 256 cols per tile. Warp w: node-subtile w>>1, 8 col-tiles.

__global__ __launch_bounds__(256) void k_node(
        const float* __restrict__ x, const float* __restrict__ sc,
        const int* __restrict__ batch, const float* __restrict__ W1,
        const float* __restrict__ b1, int N) {
    extern __shared__ char smem[];
    __half* Wc  = (__half*)smem;             // [80][256]
    __half* As  = Wc + 80 * 256;             // [64][80]
    float*  Cst = (float*)(As + 64 * 80);    // [8][256] per-warp staging
    float*  b1s = Cst + 8 * 256;             // [128]
    int tid = threadIdx.x, w = tid >> 5, lane = tid & 31;

    for (int i = tid; i < 80 * 256; i += 256) {
        int k = i >> 8, j = i & 255;
        float v = 0.f;
        if (k < 68) {
            if (j < 128) v = W1[k * 128 + j] - W1[(68 + k) * 128 + j];
            else         v = W1[(68 + k) * 128 + (j - 128)];
        }
        Wc[i] = __float2half_rn(v);
    }
    if (tid < 128) b1s[tid] = b1[tid];
    __syncthreads();

    int nt = w >> 1;            // node sub-tile 0..3 (16 nodes each)
    int cb = (w & 1) * 8;       // col-tile base (8 tiles of 16 cols)
    int ntiles = (N + 63) >> 6;
    for (int tile = blockIdx.x; tile < ntiles; tile += gridDim.x) {
        int n0 = tile << 6;
        for (int i = tid; i < 64 * 80; i += 256) {
            int nn = i / 80, k = i - nn * 80;
            int n = n0 + nn;
            float v = 0.f;
            if (n < N && k < 68)
                v = (k < 64) ? x[(size_t)n * 64 + k] : sc[batch[n] * 4 + (k - 64)];
            As[i] = __float2half_rn(v);
        }
        __syncthreads();

        wmma::fragment<wmma::accumulator, 16, 16, 16, float> fc[8];
        #pragma unroll
        for (int t = 0; t < 8; ++t) wmma::fill_fragment(fc[t], 0.f);
        #pragma unroll
        for (int kk = 0; kk < 5; ++kk) {
            wmma::fragment<wmma::matrix_a, 16, 16, 16, __half, wmma::row_major> fa;
            wmma::load_matrix_sync(fa, As + nt * 16 * 80 + kk * 16, 80);
            #pragma unroll
            for (int t = 0; t < 8; ++t) {
                wmma::fragment<wmma::matrix_b, 16, 16, 16, __half, wmma::row_major> fb;
                wmma::load_matrix_sync(fb, Wc + kk * 16 * 256 + (cb + t) * 16, 256);
                wmma::mma_sync(fc[t], fa, fb, fc[t]);
            }
        }
        #pragma unroll
        for (int t = 0; t < 8; ++t) {
            wmma::store_matrix_sync(Cst + w * 256, fc[t], 16, wmma::mem_row_major);
            __syncwarp();
            int j0 = (cb + t) * 16;
            #pragma unroll
            for (int ii = 0; ii < 4; ++ii) {
                int e = lane + ii * 32;              // pair index 0..127
                int r = e >> 3, cc = (e & 7) * 2;
                int n = n0 + nt * 16 + r;
                if (n < N) {
                    float v0 = Cst[w * 256 + r * 16 + cc];
                    float v1 = Cst[w * 256 + r * 16 + cc + 1];
                    int j = j0 + cc;
                    if (j0 < 128) {
                        __half2 h = __floats2half2_rn(v0 + b1s[j], v1 + b1s[j + 1]);
                        *(__half2*)(g_Ph + (size_t)n * 128 + j) = h;
                    } else {
                        __half2 h = __floats2half2_rn(v0, v1);
                        *(__half2*)(g_Qh + (size_t)n * 128 + (j - 128)) = h;
                    }
                }
            }
            __syncwarp();
        }
        __syncthreads();
    }
}

// ---------------- Edge aggregation: H[n] = sum_{e:dst=n} relu(P[n] + Q[src_e]) ----------------
// Uniform index loads (L1 broadcast) + 16-deep Q gather batching.

__global__ __launch_bounds__(256) void k_edge(int N) {
    int gw = (blockIdx.x * blockDim.x + threadIdx.x) >> 5;
    int lane = threadIdx.x & 31;
    if (gw >= N) return;
    int beg = g_off[gw], end = g_off[gw + 1];
    uint2 pp = *(const uint2*)(g_Ph + (size_t)gw * 128 + lane * 4);
    __half2 p0 = *(__half2*)&pp.x;
    __half2 p1 = *(__half2*)&pp.y;
    const __half2 z2 = __half2half2(__ushort_as_half(0));
    float4 acc = make_float4(0.f, 0.f, 0.f, 0.f);
    int t = beg;
    for (; t + 16 <= end; t += 16) {
        int j[16];
        #pragma unroll
        for (int u = 0; u < 16; ++u) j[u] = __ldg(&g_ssrc[t + u]);
        uint2 qq[16];
        #pragma unroll
        for (int u = 0; u < 16; ++u)
            qq[u] = *(const uint2*)(g_Qh + (size_t)j[u] * 128 + lane * 4);
        __half2 a0 = z2, a1 = z2;
        #pragma unroll
        for (int u = 0; u < 16; ++u) {
            a0 = __hadd2(a0, __hmax2(__hadd2(p0, *(__half2*)&qq[u].x), z2));
            a1 = __hadd2(a1, __hmax2(__hadd2(p1, *(__half2*)&qq[u].y), z2));
        }
        float2 f0 = __half22float2(a0), f1 = __half22float2(a1);
        acc.x += f0.x; acc.y += f0.y; acc.z += f1.x; acc.w += f1.y;
    }
    for (; t + 8 <= end; t += 8) {
        int j[8];
        #pragma unroll
        for (int u = 0; u < 8; ++u) j[u] = __ldg(&g_ssrc[t + u]);
        uint2 qq[8];
        #pragma unroll
        for (int u = 0; u < 8; ++u)
            qq[u] = *(const uint2*)(g_Qh + (size_t)j[u] * 128 + lane * 4);
        __half2 a0 = z2, a1 = z2;
        #pragma unroll
        for (int u = 0; u < 8; ++u) {
            a0 = __hadd2(a0, __hmax2(__hadd2(p0, *(__half2*)&qq[u].x), z2));
            a1 = __hadd2(a1, __hmax2(__hadd2(p1, *(__half2*)&qq[u].y), z2));
        }
        float2 f0 = __half22float2(a0), f1 = __half22float2(a1);
        acc.x += f0.x; acc.y += f0.y; acc.z += f1.x; acc.w += f1.y;
    }
    for (; t < end; ++t) {
        int j = __ldg(&g_ssrc[t]);
        uint2 qq = *(const uint2*)(g_Qh + (size_t)j * 128 + lane * 4);
        __half2 s0 = __hmax2(__hadd2(p0, *(__half2*)&qq.x), z2);
        __half2 s1 = __hmax2(__hadd2(p1, *(__half2*)&qq.y), z2);
        float2 f0 = __half22float2(s0), f1 = __half22float2(s1);
        acc.x += f0.x; acc.y += f0.y; acc.z += f1.x; acc.w += f1.y;
    }
    *(float4*)(g_H + (size_t)gw * 128 + lane * 4) = acc;
}

// ---------------- Output GEMM (tensor cores): out = H @ W2 + deg*b2 ----------------
// Block: 8 warps, 64 nodes x 128 cols per tile. Warp w: node-subtile w>>1, 4 col-tiles.

__global__ __launch_bounds__(256) void k_out(
        const float* __restrict__ W2, const float* __restrict__ b2,
        float* __restrict__ out, int N) {
    extern __shared__ char smem[];
    __half* W2h = (__half*)smem;             // [128][128]
    __half* As  = W2h + 128 * 128;           // [64][128]
    float*  Cst = (float*)(As + 64 * 128);   // [8][256]
    float*  b2s = Cst + 8 * 256;             // [128]
    float*  degs = b2s + 128;                // [64]
    int tid = threadIdx.x, w = tid >> 5, lane = tid & 31;

    for (int i = tid; i < 128 * 128; i += 256) W2h[i] = __float2half_rn(W2[i]);
    if (tid < 128) b2s[tid] = b2[tid];
    __syncthreads();

    int nt = w >> 1;            // node sub-tile 0..3
    int cb = (w & 1) * 4;       // col-tile base (4 tiles of 16 cols)
    int ntiles = (N + 63) >> 6;
    for (int tile = blockIdx.x; tile < ntiles; tile += gridDim.x) {
        int n0 = tile << 6;
        for (int i = tid; i < 64 * 32; i += 256) {
            int nn = i >> 5, q = i & 31;
            int n = n0 + nn;
            float4 v = make_float4(0.f, 0.f, 0.f, 0.f);
            if (n < N) v = *(const float4*)(g_H + (size_t)n * 128 + q * 4);
            *(__half2*)(As + nn * 128 + q * 4)     = __floats2half2_rn(v.x, v.y);
            *(__half2*)(As + nn * 128 + q * 4 + 2) = __floats2half2_rn(v.z, v.w);
        }
        if (tid < 64) {
            int n = n0 + tid;
            degs[tid] = (n < N) ? (float)(g_off[n + 1] - g_off[n]) : 0.f;
        }
        __syncthreads();

        wmma::fragment<wmma::accumulator, 16, 16, 16, float> fc[4];
        #pragma unroll
        for (int t = 0; t < 4; ++t) wmma::fill_fragment(fc[t], 0.f);
        #pragma unroll
        for (int kk = 0; kk < 8; ++kk) {
            wmma::fragment<wmma::matrix_a, 16, 16, 16, __half, wmma::row_major> fa;
            wmma::load_matrix_sync(fa, As + nt * 16 * 128 + kk * 16, 128);
            #pragma unroll
            for (int t = 0; t < 4; ++t) {
                wmma::fragment<wmma::matrix_b, 16, 16, 16, __half, wmma::row_major> fb;
                wmma::load_matrix_sync(fb, W2h + kk * 16 * 128 + (cb + t) * 16, 128);
                wmma::mma_sync(fc[t], fa, fb, fc[t]);
            }
        }
        #pragma unroll
        for (int t = 0; t < 4; ++t) {
            wmma::store_matrix_sync(Cst + w * 256, fc[t], 16, wmma::mem_row_major);
            __syncwarp();
            int j0 = (cb + t) * 16;
            #pragma unroll
            for (int ii = 0; ii < 8; ++ii) {
                int e = lane + ii * 32;            // 0..255
                int r = e >> 4, cc = e & 15;
                int n = n0 + nt * 16 + r;
                if (n < N)
                    out[(size_t)n * 128 + j0 + cc] =
                        Cst[w * 256 + r * 16 + cc] + degs[nt * 16 + r] * b2s[j0 + cc];
            }
            __syncwarp();
        }
        __syncthreads();
    }
}

// ---------------- launch ----------------

extern "C" void kernel_launch(void* const* d_in, const int* in_sizes, int n_in,
                              void* d_out, int out_size) {
    const float* x   = (const float*)d_in[0];
    const float* sc  = (const float*)d_in[1];
    const int* batch = (const int*)d_in[2];
    const int* ei    = (const int*)d_in[3];
    const float* W1  = (const float*)d_in[4];
    const float* b1  = (const float*)d_in[5];
    const float* W2  = (const float*)d_in[6];
    const float* b2  = (const float*)d_in[7];
    float* out = (float*)d_out;
    int N = in_sizes[0] / 64;
    int E = in_sizes[3] / 2;
    const int* src = ei;        // edge_index[0]
    const int* dst = ei + E;    // edge_index[1]

    const int smem_node = 80 * 256 * 2 + 64 * 80 * 2 + 8 * 256 * 4 + 128 * 4;   // 59904 B
    const int smem_out  = 128 * 128 * 2 + 64 * 128 * 2 + 8 * 256 * 4 + 128 * 4 + 64 * 4; // 58112 B

    static bool inited = false;
    static cudaStream_t s2;
    static cudaEvent_t evFork, evJoin;
    if (!inited) {
        cudaFuncSetAttribute(k_node, cudaFuncAttributeMaxDynamicSharedMemorySize, smem_node);
        cudaFuncSetAttribute(k_out,  cudaFuncAttributeMaxDynamicSharedMemorySize, smem_out);
        cudaStreamCreateWithFlags(&s2, cudaStreamNonBlocking);
        cudaEventCreateWithFlags(&evFork, cudaEventDisableTiming);
        cudaEventCreateWithFlags(&evJoin, cudaEventDisableTiming);
        inited = true;
    }

    int nb = (N + 1023) >> 10;   // 49 blocks (<= 64; all wave-1 resident for publish/spin)

    // Fork point recorded first: k_node depends only on stream state here.
    cudaEventRecord(evFork, 0);

    // CSR chain on main stream. (kernels #1, #2, #3)
    k_hist<<<(E / 8 + 255) / 256, 256>>>(dst, E);
    k_scan<<<nb, 1024>>>(N);
    k_scatter<<<(E / 4 + 255) / 256, 256>>>(src, dst, E);

    // k_node on side stream (submitted 4th -> ncu target; still starts immediately).
    cudaStreamWaitEvent(s2, evFork, 0);
    k_node<<<444, 256, smem_node, s2>>>(x, sc, batch, W1, b1, N);
    cudaEventRecord(evJoin, s2);

    // Join: k_edge needs both CSR and P/Q. (kernel #5)
    cudaStreamWaitEvent(0, evJoin, 0);
    k_edge<<<(N + 7) / 8, 256>>>(N);
    k_out<<<444, 256, smem_out>>>(W2, b2, out, N);   // kernel #6
}

// round 17
// speedup vs baseline: 1.4963x; 1.4963x over previous
#include <cuda_runtime.h>
#include <cuda_fp16.h>

typedef unsigned long long u64;

#define NMAX 50048
#define EMAX 1600000

__device__ int    g_deg[NMAX];      // statically zero; restored to zero by k_scan each call
__device__ int    g_off[NMAX + 1];
__device__ int    g_agg[64];        // re-zeroed by k_hist each call
__device__ int    g_rank[EMAX];     // within-bucket rank per edge (from hist atomics)
__device__ int    g_ssrc[EMAX];
__device__ __half g_Ph[(size_t)NMAX * 128];
__device__ __half g_Qh[(size_t)NMAX * 128];
__device__ float  g_H[(size_t)NMAX * 128];

__device__ __forceinline__ u64 pack2f(float lo, float hi) {
    u64 r; asm("mov.b64 %0, {%1, %2};" : "=l"(r) : "f"(lo), "f"(hi)); return r;
}
__device__ __forceinline__ float2 unpack2f(u64 v) {
    float2 f; asm("mov.b64 {%0, %1}, %2;" : "=f"(f.x), "=f"(f.y) : "l"(v)); return f;
}
__device__ __forceinline__ u64 ffma2(u64 a, u64 b, u64 c) {
    u64 d; asm("fma.rn.f32x2 %0, %1, %2, %3;" : "=l"(d) : "l"(a), "l"(b), "l"(c)); return d;
}
__device__ __forceinline__ unsigned int smem_u32(const void* p) {
    return (unsigned int)__cvta_generic_to_shared(p);
}

// ---------------- CSR build ----------------

// 8 edges/thread. Atomic returns = within-bucket rank, stored coalesced (int4).
__global__ void k_hist(const int* __restrict__ dst, int E) {
    if (blockIdx.x == 0 && threadIdx.x < 64) g_agg[threadIdx.x] = 0;
    int i0 = (blockIdx.x * blockDim.x + threadIdx.x) * 8;
    if (i0 + 7 < E) {
        int4 d0 = *(const int4*)(dst + i0);
        int4 d1 = *(const int4*)(dst + i0 + 4);
        int4 r0, r1;
        r0.x = atomicAdd(&g_deg[d0.x], 1);
        r0.y = atomicAdd(&g_deg[d0.y], 1);
        r0.z = atomicAdd(&g_deg[d0.z], 1);
        r0.w = atomicAdd(&g_deg[d0.w], 1);
        r1.x = atomicAdd(&g_deg[d1.x], 1);
        r1.y = atomicAdd(&g_deg[d1.y], 1);
        r1.z = atomicAdd(&g_deg[d1.z], 1);
        r1.w = atomicAdd(&g_deg[d1.w], 1);
        *(int4*)(g_rank + i0) = r0;
        *(int4*)(g_rank + i0 + 4) = r1;
    } else {
        for (int i = i0; i < E; ++i) g_rank[i] = atomicAdd(&g_deg[dst[i]], 1);
    }
}

// Single-pass exclusive scan over g_deg (nb <= 64 blocks, all wave-1 resident).
__global__ void k_scan(int N) {
    int idx = blockIdx.x * 1024 + threadIdx.x;
    int lane = threadIdx.x & 31, wid = threadIdx.x >> 5;
    int v = (idx < N) ? g_deg[idx] : 0;
    if (idx < N) g_deg[idx] = 0;   // restore initial state for next invocation
    int val = v;
    #pragma unroll
    for (int d = 1; d < 32; d <<= 1) {
        int t = __shfl_up_sync(0xffffffffu, val, d);
        if (lane >= d) val += t;
    }
    __shared__ int ws[32];
    __shared__ int partial[2];
    if (lane == 31) ws[wid] = val;
    __syncthreads();
    if (wid == 0) {
        int s = ws[lane];
        #pragma unroll
        for (int d = 1; d < 32; d <<= 1) {
            int t = __shfl_up_sync(0xffffffffu, s, d);
            if (lane >= d) s += t;
        }
        ws[lane] = s;
        if (lane == 31) atomicExch(&g_agg[blockIdx.x], s + 1);  // publish block total
    }
    if (threadIdx.x < 64) {
        int a = 0;
        if (threadIdx.x < blockIdx.x) {
            while ((a = atomicAdd(&g_agg[threadIdx.x], 0)) == 0) { }
            a -= 1;
        }
        #pragma unroll
        for (int d = 16; d > 0; d >>= 1) a += __shfl_down_sync(0xffffffffu, a, d);
        if (lane == 0) partial[wid] = a;
    }
    __syncthreads();
    int base = partial[0] + partial[1] + (wid ? ws[wid - 1] : 0);
    int excl = base + val - v;
    if (idx < N) g_off[idx] = excl;
    if (idx == N - 1) g_off[N] = excl + v;
}

// Atomic-free scatter: pos = off[dst] + rank. Pure loads + random store, MLP=4.
__global__ void k_scatter(const int* __restrict__ src, const int* __restrict__ dst, int E) {
    int i0 = (blockIdx.x * blockDim.x + threadIdx.x) * 4;
    if (i0 + 3 < E) {
        int4 d = *(const int4*)(dst + i0);
        int4 r = *(const int4*)(g_rank + i0);
        int4 s = *(const int4*)(src + i0);
        int p0 = g_off[d.x] + r.x;
        int p1 = g_off[d.y] + r.y;
        int p2 = g_off[d.z] + r.z;
        int p3 = g_off[d.w] + r.w;
        g_ssrc[p0] = s.x;
        g_ssrc[p1] = s.y;
        g_ssrc[p2] = s.z;
        g_ssrc[p3] = s.w;
    } else {
        for (int i = i0; i < E; ++i)
            g_ssrc[g_off[dst[i]] + g_rank[i]] = src[i];
    }
}

// ---------------- Node transform: P = h@(W1a-W1b)+b1, Q = h@W1b (stored fp16) ----------------
// R14 version: 2 cols/thread (c, c+64); 4 thread-groups x 8 nodes = 32 nodes/tile.

__global__ __launch_bounds__(256, 2) void k_node(
        const float* __restrict__ x, const float* __restrict__ sc,
        const int* __restrict__ batch, const float* __restrict__ W1,
        const float* __restrict__ b1, int N) {
    extern __shared__ char smem[];
    ulonglong2* Wd2 = (ulonglong2*)smem;       // 17*128 quads of (W1a - W1b)
    ulonglong2* Wb2 = Wd2 + 17 * 128;          // 17*128 quads of W1b
    float* hs = (float*)(Wb2 + 17 * 128);      // 32 nodes * 68 feats
    float* b1s = hs + 32 * 68;                 // 128
    int tid = threadIdx.x;                     // 256 threads
    int cs = tid & 63, grp = tid >> 6;
    int c0 = cs, c1 = cs + 64;

    for (int i = tid; i < 17 * 128; i += 256) {
        int g = i >> 7, cc = i & 127;
        int k0 = 4 * g;
        float a0 = W1[(k0 + 0) * 128 + cc];
        float a1 = W1[(k0 + 1) * 128 + cc];
        float a2 = W1[(k0 + 2) * 128 + cc];
        float a3 = W1[(k0 + 3) * 128 + cc];
        float q0 = W1[(68 + k0 + 0) * 128 + cc];
        float q1 = W1[(68 + k0 + 1) * 128 + cc];
        float q2 = W1[(68 + k0 + 2) * 128 + cc];
        float q3 = W1[(68 + k0 + 3) * 128 + cc];
        ulonglong2 wd, wb;
        wd.x = pack2f(a0 - q0, a1 - q1);
        wd.y = pack2f(a2 - q2, a3 - q3);
        wb.x = pack2f(q0, q1);
        wb.y = pack2f(q2, q3);
        Wd2[i] = wd;
        Wb2[i] = wb;
    }
    if (tid < 128) b1s[tid] = b1[tid];
    __syncthreads();

    int ntiles = (N + 31) >> 5;
    for (int tile = blockIdx.x; tile < ntiles; tile += gridDim.x) {
        int n0 = tile << 5;
        for (int i = tid; i < 32 * 68; i += 256) {
            int nn = i / 68, k = i - nn * 68;
            int n = n0 + nn;
            float v = 0.f;
            if (n < N) v = (k < 64) ? x[(size_t)n * 64 + k] : sc[batch[n] * 4 + (k - 64)];
            hs[i] = v;
        }
        __syncthreads();
        const float* hb = hs + grp * 8 * 68;
        u64 aP0[8], aP1[8], aQ0[8], aQ1[8];
        #pragma unroll
        for (int nn = 0; nn < 8; ++nn) {
            aP0[nn] = pack2f(b1s[c0], 0.f);
            aP1[nn] = pack2f(b1s[c1], 0.f);
            aQ0[nn] = pack2f(0.f, 0.f);
            aQ1[nn] = pack2f(0.f, 0.f);
        }
        #pragma unroll
        for (int g = 0; g < 17; ++g) {
            ulonglong2 wd0 = Wd2[g * 128 + c0];
            ulonglong2 wd1 = Wd2[g * 128 + c1];
            ulonglong2 wb0 = Wb2[g * 128 + c0];
            ulonglong2 wb1 = Wb2[g * 128 + c1];
            #pragma unroll
            for (int nn = 0; nn < 8; ++nn) {
                ulonglong2 hh = *(const ulonglong2*)(hb + nn * 68 + 4 * g);
                aP0[nn] = ffma2(wd0.x, hh.x, aP0[nn]);
                aP0[nn] = ffma2(wd0.y, hh.y, aP0[nn]);
                aQ0[nn] = ffma2(wb0.x, hh.x, aQ0[nn]);
                aQ0[nn] = ffma2(wb0.y, hh.y, aQ0[nn]);
                aP1[nn] = ffma2(wd1.x, hh.x, aP1[nn]);
                aP1[nn] = ffma2(wd1.y, hh.y, aP1[nn]);
                aQ1[nn] = ffma2(wb1.x, hh.x, aQ1[nn]);
                aQ1[nn] = ffma2(wb1.y, hh.y, aQ1[nn]);
            }
        }
        #pragma unroll
        for (int nn = 0; nn < 8; ++nn) {
            int n = n0 + grp * 8 + nn;
            if (n < N) {
                float2 f;
                f = unpack2f(aP0[nn]); g_Ph[(size_t)n * 128 + c0] = __float2half_rn(f.x + f.y);
                f = unpack2f(aP1[nn]); g_Ph[(size_t)n * 128 + c1] = __float2half_rn(f.x + f.y);
                f = unpack2f(aQ0[nn]); g_Qh[(size_t)n * 128 + c0] = __float2half_rn(f.x + f.y);
                f = unpack2f(aQ1[nn]); g_Qh[(size_t)n * 128 + c1] = __float2half_rn(f.x + f.y);
            }
        }
        __syncthreads();
    }
}

// ---------------- Edge aggregation: H[n] = sum_{e:dst=n} relu(P[n] + Q[src_e]) ----------------

__global__ __launch_bounds__(256) void k_edge(int N) {
    int gw = (blockIdx.x * blockDim.x + threadIdx.x) >> 5;
    int lane = threadIdx.x & 31;
    if (gw >= N) return;
    int beg = g_off[gw], end = g_off[gw + 1];
    uint2 pp = *(const uint2*)(g_Ph + (size_t)gw * 128 + lane * 4);
    __half2 p0 = *(__half2*)&pp.x;
    __half2 p1 = *(__half2*)&pp.y;
    const __half2 z2 = __half2half2(__ushort_as_half(0));
    float4 acc = make_float4(0.f, 0.f, 0.f, 0.f);
    int t = beg;
    for (; t + 16 <= end; t += 16) {
        int j[16];
        #pragma unroll
        for (int u = 0; u < 16; ++u) j[u] = __ldg(&g_ssrc[t + u]);
        uint2 qq[16];
        #pragma unroll
        for (int u = 0; u < 16; ++u)
            qq[u] = *(const uint2*)(g_Qh + (size_t)j[u] * 128 + lane * 4);
        __half2 a0 = z2, a1 = z2;
        #pragma unroll
        for (int u = 0; u < 16; ++u) {
            a0 = __hadd2(a0, __hmax2(__hadd2(p0, *(__half2*)&qq[u].x), z2));
            a1 = __hadd2(a1, __hmax2(__hadd2(p1, *(__half2*)&qq[u].y), z2));
        }
        float2 f0 = __half22float2(a0), f1 = __half22float2(a1);
        acc.x += f0.x; acc.y += f0.y; acc.z += f1.x; acc.w += f1.y;
    }
    for (; t + 8 <= end; t += 8) {
        int j[8];
        #pragma unroll
        for (int u = 0; u < 8; ++u) j[u] = __ldg(&g_ssrc[t + u]);
        uint2 qq[8];
        #pragma unroll
        for (int u = 0; u < 8; ++u)
            qq[u] = *(const uint2*)(g_Qh + (size_t)j[u] * 128 + lane * 4);
        __half2 a0 = z2, a1 = z2;
        #pragma unroll
        for (int u = 0; u < 8; ++u) {
            a0 = __hadd2(a0, __hmax2(__hadd2(p0, *(__half2*)&qq[u].x), z2));
            a1 = __hadd2(a1, __hmax2(__hadd2(p1, *(__half2*)&qq[u].y), z2));
        }
        float2 f0 = __half22float2(a0), f1 = __half22float2(a1);
        acc.x += f0.x; acc.y += f0.y; acc.z += f1.x; acc.w += f1.y;
    }
    for (; t < end; ++t) {
        int j = __ldg(&g_ssrc[t]);
        uint2 qq = *(const uint2*)(g_Qh + (size_t)j * 128 + lane * 4);
        __half2 s0 = __hmax2(__hadd2(p0, *(__half2*)&qq.x), z2);
        __half2 s1 = __hmax2(__hadd2(p1, *(__half2*)&qq.y), z2);
        float2 f0 = __half22float2(s0), f1 = __half22float2(s1);
        acc.x += f0.x; acc.y += f0.y; acc.z += f1.x; acc.w += f1.y;
    }
    *(float4*)(g_H + (size_t)gw * 128 + lane * 4) = acc;
}

// ---------------- Output GEMM (raw mma.sync): out = H @ W2 + deg*b2 ----------------
// Documented m16n8k16 fragment layouts -> register epilogue, zero staging.
// 8 warps; warp w owns cols [w*16, w*16+16) (two n8 frags). B preloaded in regs.
// Smem rows padded to 136 halves (bank-conflict-free ldmatrix).

__global__ __launch_bounds__(256, 3) void k_out(
        const float* __restrict__ W2, const float* __restrict__ b2,
        float* __restrict__ out, int N) {
    extern __shared__ char smem[];
    __half* W2h  = (__half*)smem;               // [128][136]
    __half* As   = W2h + 128 * 136;             // [16][136]
    float*  b2s  = (float*)(As + 16 * 136);     // [128]
    float*  degs = b2s + 128;                   // [16]
    int tid = threadIdx.x, w = tid >> 5, lane = tid & 31;
    int tg = lane & 3, g = lane >> 2;

    // Stage W2 as fp16 (padded rows)
    for (int i = tid; i < 128 * 128; i += 256) {
        int k = i >> 7, n = i & 127;
        W2h[k * 136 + n] = __float2half_rn(W2[i]);
    }
    if (tid < 128) b2s[tid] = b2[tid];
    __syncthreads();

    // Preload B fragments (weights constant across tiles): 8 k-steps x 2 n8-frags
    int nc = w * 16;
    unsigned int bf[8][2][2];
    #pragma unroll
    for (int kk = 0; kk < 8; ++kk) {
        #pragma unroll
        for (int nf = 0; nf < 2; ++nf) {
            unsigned int addr = smem_u32(W2h + (kk * 16 + (lane & 15)) * 136 + nc + nf * 8);
            asm volatile("ldmatrix.sync.aligned.m8n8.x2.trans.shared.b16 {%0,%1}, [%2];"
                         : "=r"(bf[kk][nf][0]), "=r"(bf[kk][nf][1]) : "r"(addr));
        }
    }
    float bb00 = b2s[nc + tg * 2],     bb01 = b2s[nc + tg * 2 + 1];
    float bb10 = b2s[nc + 8 + tg * 2], bb11 = b2s[nc + 8 + tg * 2 + 1];
    __syncthreads();

    int ntiles = (N + 15) >> 4;
    for (int tile = blockIdx.x; tile < ntiles; tile += gridDim.x) {
        int n0 = tile << 4;
        // Stage H (fp32 -> fp16, padded rows) + degs
        for (int i = tid; i < 16 * 32; i += 256) {
            int nn = i >> 5, q = i & 31;
            int n = n0 + nn;
            float4 v = make_float4(0.f, 0.f, 0.f, 0.f);
            if (n < N) v = *(const float4*)(g_H + (size_t)n * 128 + q * 4);
            *(__half2*)(As + nn * 136 + q * 4)     = __floats2half2_rn(v.x, v.y);
            *(__half2*)(As + nn * 136 + q * 4 + 2) = __floats2half2_rn(v.z, v.w);
        }
        if (tid < 16) {
            int n = n0 + tid;
            degs[tid] = (n < N) ? (float)(g_off[n + 1] - g_off[n]) : 0.f;
        }
        __syncthreads();

        float d0[4] = {0.f, 0.f, 0.f, 0.f};
        float d1[4] = {0.f, 0.f, 0.f, 0.f};
        unsigned int a_base = smem_u32(As + (lane & 15) * 136 + ((lane >> 4) << 3));
        #pragma unroll
        for (int kk = 0; kk < 8; ++kk) {
            unsigned int a[4];
            asm volatile("ldmatrix.sync.aligned.m8n8.x4.shared.b16 {%0,%1,%2,%3}, [%4];"
                         : "=r"(a[0]), "=r"(a[1]), "=r"(a[2]), "=r"(a[3])
                         : "r"(a_base + kk * 32));
            asm volatile("mma.sync.aligned.m16n8k16.row.col.f32.f16.f16.f32 "
                         "{%0,%1,%2,%3}, {%4,%5,%6,%7}, {%8,%9}, {%0,%1,%2,%3};"
                         : "+f"(d0[0]), "+f"(d0[1]), "+f"(d0[2]), "+f"(d0[3])
                         : "r"(a[0]), "r"(a[1]), "r"(a[2]), "r"(a[3]),
                           "r"(bf[kk][0][0]), "r"(bf[kk][0][1]));
            asm volatile("mma.sync.aligned.m16n8k16.row.col.f32.f16.f16.f32 "
                         "{%0,%1,%2,%3}, {%4,%5,%6,%7}, {%8,%9}, {%0,%1,%2,%3};"
                         : "+f"(d1[0]), "+f"(d1[1]), "+f"(d1[2]), "+f"(d1[3])
                         : "r"(a[0]), "r"(a[1]), "r"(a[2]), "r"(a[3]),
                           "r"(bf[kk][1][0]), "r"(bf[kk][1][1]));
        }
        // Register epilogue: d + deg*b2, direct float2 stores
        float dgA = degs[g], dgB = degs[g + 8];
        int nA = n0 + g, nB = n0 + g + 8;
        if (nA < N) {
            float2 v;
            v.x = d0[0] + dgA * bb00; v.y = d0[1] + dgA * bb01;
            *(float2*)(out + (size_t)nA * 128 + nc + tg * 2) = v;
            v.x = d1[0] + dgA * bb10; v.y = d1[1] + dgA * bb11;
            *(float2*)(out + (size_t)nA * 128 + nc + 8 + tg * 2) = v;
        }
        if (nB < N) {
            float2 v;
            v.x = d0[2] + dgB * bb00; v.y = d0[3] + dgB * bb01;
            *(float2*)(out + (size_t)nB * 128 + nc + tg * 2) = v;
            v.x = d1[2] + dgB * bb10; v.y = d1[3] + dgB * bb11;
            *(float2*)(out + (size_t)nB * 128 + nc + 8 + tg * 2) = v;
        }
        __syncthreads();
    }
}

// ---------------- launch ----------------

extern "C" void kernel_launch(void* const* d_in, const int* in_sizes, int n_in,
                              void* d_out, int out_size) {
    const float* x   = (const float*)d_in[0];
    const float* sc  = (const float*)d_in[1];
    const int* batch = (const int*)d_in[2];
    const int* ei    = (const int*)d_in[3];
    const float* W1  = (const float*)d_in[4];
    const float* b1  = (const float*)d_in[5];
    const float* W2  = (const float*)d_in[6];
    const float* b2  = (const float*)d_in[7];
    float* out = (float*)d_out;
    int N = in_sizes[0] / 64;
    int E = in_sizes[3] / 2;
    const int* src = ei;        // edge_index[0]
    const int* dst = ei + E;    // edge_index[1]

    const int smem_node = 2 * 17 * 128 * 16 + 32 * 68 * 4 + 128 * 4;          // 78848 B
    const int smem_out  = 128 * 136 * 2 + 16 * 136 * 2 + 128 * 4 + 16 * 4;    // 39744 B

    static bool inited = false;
    static cudaStream_t s2;
    static cudaEvent_t evFork, evJoin;
    if (!inited) {
        cudaFuncSetAttribute(k_node, cudaFuncAttributeMaxDynamicSharedMemorySize, smem_node);
        cudaFuncSetAttribute(k_out,  cudaFuncAttributeMaxDynamicSharedMemorySize, smem_out);
        cudaStreamCreateWithFlags(&s2, cudaStreamNonBlocking);
        cudaEventCreateWithFlags(&evFork, cudaEventDisableTiming);
        cudaEventCreateWithFlags(&evJoin, cudaEventDisableTiming);
        inited = true;
    }

    int nb = (N + 1023) >> 10;   // 49 blocks (<= 64; all wave-1 resident for publish/spin)

    // Fork point recorded first: k_node depends only on stream state here.
    cudaEventRecord(evFork, 0);

    // CSR chain on main stream. (kernels #1, #2, #3)
    k_hist<<<(E / 8 + 255) / 256, 256>>>(dst, E);
    k_scan<<<nb, 1024>>>(N);
    k_scatter<<<(E / 4 + 255) / 256, 256>>>(src, dst, E);

    // k_node on side stream (submitted 4th -> ncu target; still starts immediately).
    cudaStreamWaitEvent(s2, evFork, 0);
    k_node<<<296, 256, smem_node, s2>>>(x, sc, batch, W1, b1, N);
    cudaEventRecord(evJoin, s2);

    // Join: k_edge needs both CSR and P/Q. (kernel #5)
    cudaStreamWaitEvent(0, evJoin, 0);
    k_edge<<<(N + 7) / 8, 256>>>(N);
    k_out<<<444, 256, smem_out>>>(W2, b2, out, N);   // kernel #6
}